// round 6
// baseline (speedup 1.0000x reference)
#include <cuda_runtime.h>
#include <cuda_fp16.h>

// ---------------- problem constants ----------------
#define B_    4
#define CIN   256
#define H_    56
#define W_    56
#define HW    3136
#define OUT_  256
#define WS_   32
#define K2    49
#define KP    52
#define MPROJ 288
#define PC_   272
#define PH    62
#define PW    64

// ---------------- scratch (device globals) --------------------------------
__device__ float  g_wc[MPROJ * CIN];
__device__ float  g_bc[MPROJ];
__device__ float  g_s1[16], g_t1[16];
__device__ float  g_cw1t[256];     // [c][o] transposed
__device__ float  g_cw2t[512];     // [o][g] transposed
__device__ float  g_proj[B_ * MPROJ * HW];
__device__ float  g_pad[(size_t)B_ * PC_ * PH * PW];
__device__ __half g_w[(size_t)B_ * WS_ * HW * KP];
__device__ float  g_agg[B_ * OUT_ * HW];

__device__ __forceinline__ int refl(int i, int n) {
    if (i < 0) i = -i;
    if (i >= n) i = 2 * n - 2 - i;
    return i;
}

// ---------------- kernel 0: pack weights + bn1 fold + transposes ----------
__global__ void pack_kernel(const float* __restrict__ w1, const float* __restrict__ b1,
                            const float* __restrict__ w2, const float* __restrict__ b2,
                            const float* __restrict__ w3, const float* __restrict__ b3,
                            const float* __restrict__ bn1g, const float* __restrict__ bn1b,
                            const float* __restrict__ bn1m, const float* __restrict__ bn1v,
                            const float* __restrict__ cw1, const float* __restrict__ cw2) {
    int i = blockIdx.x * blockDim.x + threadIdx.x;
    if (i < MPROJ * CIN) {
        int r = i / CIN, c = i % CIN;
        float v;
        if (r < 16)      v = w1[r * CIN + c];
        else if (r < 32) v = w2[(r - 16) * CIN + c];
        else             v = w3[(r - 32) * CIN + c];
        g_wc[i] = v;
    }
    if (i < MPROJ) {
        g_bc[i] = (i < 16) ? b1[i] : ((i < 32) ? b2[i - 16] : b3[i - 32]);
    }
    if (i < 16) {
        float s = bn1g[i] * rsqrtf(bn1v[i] + 1e-5f);
        g_s1[i] = s;
        g_t1[i] = bn1b[i] - s * bn1m[i];
    }
    if (i < 256) g_cw1t[i] = cw1[(i & 15) * 16 + (i >> 4)];    // [c][o]
    if (i < 512) g_cw2t[i] = cw2[(i & 31) * 16 + (i >> 5)];    // [o][g]
}

// ---------------- kernel 1: projection GEMM (double-buffered) -------------
#define BM 96
#define BN 64
#define BK 16
__global__ __launch_bounds__(256) void proj_gemm(const float* __restrict__ x) {
    __shared__ float As[2][BK][BM + 1];
    __shared__ __align__(16) float Bs[2][BK][BN];

    int b  = blockIdx.z;
    int m0 = blockIdx.y * BM;
    int n0 = blockIdx.x * BN;
    int t  = threadIdx.x;
    int tx = t & 15;
    int ty = t >> 4;

    const float* xb = x + (size_t)b * CIN * HW;

    // per-thread load coords
    int la_col = t & 15;            // A: 6 elems, rows (t>>4) + q*16? (see below)
    int lb_row = t >> 4, lb_cg = t & 15;

    float acc[6][4];
#pragma unroll
    for (int i = 0; i < 6; i++)
#pragma unroll
        for (int j = 0; j < 4; j++) acc[i][j] = 0.0f;

    // preload tile 0 into buffer 0
    float aReg[6];
    float4 bReg;
#pragma unroll
    for (int q = 0; q < 6; q++) {
        int idx = t + q * 256;
        aReg[q] = g_wc[(m0 + (idx >> 4)) * CIN + (idx & 15)];
    }
    bReg = *reinterpret_cast<const float4*>(&xb[(size_t)lb_row * HW + n0 + lb_cg * 4]);
#pragma unroll
    for (int q = 0; q < 6; q++) {
        int idx = t + q * 256;
        As[0][idx & 15][idx >> 4] = aReg[q];
    }
    *reinterpret_cast<float4*>(&Bs[0][lb_row][lb_cg * 4]) = bReg;
    __syncthreads();

    for (int it = 0; it < CIN / BK; it++) {
        int cur = it & 1, nxt = cur ^ 1;
        int k1 = (it + 1) * BK;
        if (k1 < CIN) {
#pragma unroll
            for (int q = 0; q < 6; q++) {
                int idx = t + q * 256;
                aReg[q] = g_wc[(m0 + (idx >> 4)) * CIN + k1 + (idx & 15)];
            }
            bReg = *reinterpret_cast<const float4*>(&xb[(size_t)(k1 + lb_row) * HW + n0 + lb_cg * 4]);
        }
#pragma unroll
        for (int k = 0; k < BK; k++) {
            float a[6];
#pragma unroll
            for (int i = 0; i < 6; i++) a[i] = As[cur][k][ty * 6 + i];
            float4 bv = *reinterpret_cast<float4*>(&Bs[cur][k][tx * 4]);
            float bb[4] = {bv.x, bv.y, bv.z, bv.w};
#pragma unroll
            for (int i = 0; i < 6; i++)
#pragma unroll
                for (int j = 0; j < 4; j++) acc[i][j] = fmaf(a[i], bb[j], acc[i][j]);
        }
        if (k1 < CIN) {
#pragma unroll
            for (int q = 0; q < 6; q++) {
                int idx = t + q * 256;
                As[nxt][idx & 15][idx >> 4] = aReg[q];
            }
            *reinterpret_cast<float4*>(&Bs[nxt][lb_row][lb_cg * 4]) = bReg;
        }
        __syncthreads();
    }

#pragma unroll
    for (int i = 0; i < 6; i++) {
        int m = m0 + ty * 6 + i;
        float bias = g_bc[m];
        float vv[4];
#pragma unroll
        for (int j = 0; j < 4; j++) vv[j] = acc[i][j] + bias;
        if (m < 16) {
            float s = g_s1[m], tt = g_t1[m];
#pragma unroll
            for (int j = 0; j < 4; j++) vv[j] = fmaf(s, vv[j], tt);
        } else if (m < 32) {
            float s = g_s1[m - 16];
#pragma unroll
            for (int j = 0; j < 4; j++) vv[j] *= s;
        }
        float4 v = make_float4(vv[0], vv[1], vv[2], vv[3]);
        *reinterpret_cast<float4*>(&g_proj[((size_t)b * MPROJ + m) * HW + n0 + tx * 4]) = v;
    }
}

// ---------------- kernel 1b: reflect-pad channels 16..287 -----------------
__global__ void pad_kernel() {
    int idx = blockIdx.x * 256 + threadIdx.x;
    const int total = B_ * PC_ * PH * PW;
    if (idx >= total) return;
    int col = idx & 63;
    int rest = idx >> 6;
    int r = rest % PH;
    int cb = rest / PH;
    int c = cb % PC_;
    int b = cb / PC_;
    int oy = refl(r - 3, H_), ox = refl(col - 3, W_);
    g_pad[idx] = g_proj[((size_t)(b * MPROJ + 16 + c)) * HW + oy * W_ + ox];
}

// ---------------- kernel 2: attention weights + softmax -------------------
__global__ __launch_bounds__(224, 5) void attn_kernel(
    const float* __restrict__ bn2g, const float* __restrict__ bn2b,
    const float* __restrict__ bn2m, const float* __restrict__ bn2v,
    const float* __restrict__ cb) {

    __shared__ __align__(16) float sx2[16 * 84];
    __shared__ float sx1[64];
    __shared__ __align__(16) float act0[196 * 16];
    __shared__ __align__(4) __half slog[4 * 32 * 52];
    __shared__ float s2s[16], t2s[16];
    __shared__ __align__(16) float scw1t[256];
    __shared__ __align__(16) float scw2t[512];
    __shared__ float scb[32];
    __shared__ float sinv[128];

    int t = threadIdx.x;
    int b = blockIdx.y;
    int p0 = blockIdx.x * 4;
    int h = p0 / W_, w0 = p0 % W_;

    if (t < 16) {
        float ss = bn2g[t] * rsqrtf(bn2v[t] + 1e-5f);
        s2s[t] = ss; t2s[t] = bn2b[t] - ss * bn2m[t];
    }
    // linear float4 weight staging (pre-transposed in pack)
    if (t < 64)
        reinterpret_cast<float4*>(scw1t)[t] = reinterpret_cast<const float4*>(g_cw1t)[t];
    else if (t < 192)
        reinterpret_cast<float4*>(scw2t)[t - 64] = reinterpret_cast<const float4*>(g_cw2t)[t - 64];
    if (t < 32) scb[t] = cb[t];
    if (t >= 192 && t < 224) {
        int idx = (t - 192) * 2;
        int pix = idx >> 4, c = idx & 15;
        const float* bp = g_proj + (size_t)b * MPROJ * HW;
        sx1[idx]     = bp[c * HW + p0 + pix];
        sx1[idx + 1] = bp[(c + 1) * HW + p0 + pix];
    }
    const float* padb = g_pad + (size_t)b * PC_ * PH * PW;
    for (int i = t; i < 336; i += 224) {
        int c = i / 21, rem = i - c * 21, dy = rem / 3, cg = rem - dy * 3;
        float4 v = *reinterpret_cast<const float4*>(
            padb + ((size_t)c * PH + h + dy) * PW + w0 + cg * 4);
        *reinterpret_cast<float4*>(sx2 + c * 84 + dy * 12 + cg * 4) = v;
    }
    __syncthreads();

    // phase1: stage1 activation relu(x1' - x2')
    if (t < 196) {
        int pix = t / 49, k = t - pix * 49;
        int dy = k / 7, dx = k - dy * 7;
        const float* x2p = sx2 + dy * 12 + dx + pix;
        const float* x1p = sx1 + pix * 16;
        float av[16];
#pragma unroll
        for (int c = 0; c < 16; c++) av[c] = fmaxf(x1p[c] - x2p[c * 84], 0.0f);
        float4* dst = reinterpret_cast<float4*>(act0 + t * 16);
#pragma unroll
        for (int q = 0; q < 4; q++)
            dst[q] = make_float4(av[q * 4], av[q * 4 + 1], av[q * 4 + 2], av[q * 4 + 3]);
    }
    __syncthreads();

    // phase2: GEMM1 + BN2 + ReLU in place; thread = (o-pair, pb 0..27)
    {
        int op = t & 7, pb = t >> 3;
        int o0 = op * 2;
        float2 w1r[16];
#pragma unroll
        for (int c = 0; c < 16; c++)
            w1r[c] = *reinterpret_cast<const float2*>(scw1t + c * 16 + o0);
        float s2a = s2s[o0], s2b = s2s[o0 + 1];
        float t2a = t2s[o0], t2b = t2s[o0 + 1];
        float* ab = act0 + pb * 16;
#pragma unroll
        for (int n = 0; n < 7; n++) {
            const float4* ap = reinterpret_cast<const float4*>(ab + n * 448);
            float a[16];
            *reinterpret_cast<float4*>(a + 0)  = ap[0];
            *reinterpret_cast<float4*>(a + 4)  = ap[1];
            *reinterpret_cast<float4*>(a + 8)  = ap[2];
            *reinterpret_cast<float4*>(a + 12) = ap[3];
            float h0 = 0.0f, h1 = 0.0f;
#pragma unroll
            for (int c = 0; c < 16; c++) {
                h0 = fmaf(a[c], w1r[c].x, h0);
                h1 = fmaf(a[c], w1r[c].y, h1);
            }
            __syncwarp();
            float r0 = fmaxf(fmaf(s2a, h0, t2a), 0.0f);
            float r1 = fmaxf(fmaf(s2b, h1, t2b), 0.0f);
            *reinterpret_cast<float2*>(ab + n * 448 + o0) = make_float2(r0, r1);
            __syncwarp();
        }
    }
    __syncthreads();

    // phase3: GEMM2 + bias -> fp16 logits; thread = (g-pair, pb 0..13)
    {
        int gp = t & 15, pb = t >> 4;
        int g0 = gp * 2;
        float2 w2r[16];
#pragma unroll
        for (int o = 0; o < 16; o++)
            w2r[o] = *reinterpret_cast<const float2*>(scw2t + o * 32 + g0);
        float bias0 = scb[g0], bias1 = scb[g0 + 1];
        int pix = 0, k = pb;              // pt = pb + 14n, incremental
        const float* ab = act0 + pb * 16;
#pragma unroll
        for (int n = 0; n < 14; n++) {
            const float4* ap = reinterpret_cast<const float4*>(ab + n * 224);
            float a[16];
            *reinterpret_cast<float4*>(a + 0)  = ap[0];
            *reinterpret_cast<float4*>(a + 4)  = ap[1];
            *reinterpret_cast<float4*>(a + 8)  = ap[2];
            *reinterpret_cast<float4*>(a + 12) = ap[3];
            float h0 = bias0, h1 = bias1;
#pragma unroll
            for (int o = 0; o < 16; o++) {
                h0 = fmaf(a[o], w2r[o].x, h0);
                h1 = fmaf(a[o], w2r[o].y, h1);
            }
            int rowb = (pix * 32 + g0) * 52 + k;
            slog[rowb]      = __float2half(h0);
            slog[rowb + 52] = __float2half(h1);
            k += 14;
            if (k >= 49) { k -= 49; pix++; }
        }
    }
    __syncthreads();

    // phase4: softmax over 49 taps (exp in place, keep 1/sum)
    if (t < 128) {
        __half2* row = reinterpret_cast<__half2*>(slog) + t * 26;
        float m = -1e30f;
#pragma unroll
        for (int k2 = 0; k2 < 24; k2++) {
            float2 f = __half22float2(row[k2]);
            m = fmaxf(m, fmaxf(f.x, f.y));
        }
        m = fmaxf(m, __half22float2(row[24]).x);
        float s = 0.0f;
#pragma unroll
        for (int k2 = 0; k2 < 24; k2++) {
            float2 f = __half22float2(row[k2]);
            float ex = __expf(f.x - m), ey = __expf(f.y - m);
            s += ex + ey;
            row[k2] = __floats2half2_rn(ex, ey);
        }
        {
            float ex = __expf(__half22float2(row[24]).x - m);
            s += ex;
            row[24] = __floats2half2_rn(ex, 0.0f);
            row[25] = __floats2half2_rn(0.0f, 0.0f);
        }
        sinv[t] = 1.0f / s;
    }
    __syncthreads();

    // phase5: scale + write fp16 g_w, division-free index tracking
    {
        __half2* gw2 = reinterpret_cast<__half2*>(g_w);
        const __half2* sl2 = reinterpret_cast<const __half2*>(slog);
        int g = 0, rem = t;
        while (rem >= 104) { rem -= 104; g++; }
        for (int i = t; i < 3328; i += 224) {
            int pix = (rem >= 52) ? ((rem >= 78) ? 3 : 2) : ((rem >= 26) ? 1 : 0);
            int k2 = rem - pix * 26;
            int r = pix * 32 + g;
            float2 f = __half22float2(sl2[r * 26 + k2]);
            float inv = sinv[r];
            gw2[(((size_t)(b * WS_ + g)) * HW + p0 + pix) * 26 + k2] =
                __floats2half2_rn(f.x * inv, f.y * inv);
            rem += 16; g += 2;
            if (rem >= 104) { rem -= 104; g++; }
        }
    }
}

// ---------------- kernel 3: aggregation -----------------------------------
__global__ __launch_bounds__(128) void agg_kernel() {
    __shared__ __align__(4) __half swh[64 * KP];
    __shared__ __align__(16) float sx3[8 * 14 * 24];

    int b = blockIdx.z, g = blockIdx.y, tile = blockIdx.x;
    int ty0 = (tile / 7) * 8, tx0 = (tile % 7) * 8;
    int t = threadIdx.x;

    const __half2* gw2 = reinterpret_cast<const __half2*>(g_w);
    size_t wbase = ((size_t)(b * WS_ + g)) * HW;
    for (int i = t; i < 1664; i += 128) {
        int run = i / 208, off = i - run * 208;
        reinterpret_cast<__half2*>(swh)[run * 208 + off] =
            gw2[(wbase + (ty0 + run) * W_ + tx0) * 26 + off];
    }
    const float* padb = g_pad + ((size_t)(b * PC_) + 16 + g * 8) * PH * PW;
    for (int i = t; i < 448; i += 128) {
        int c = i / 56, rem = i - c * 56, r = rem >> 2, cg = rem & 3;
        float4 v = *reinterpret_cast<const float4*>(
            padb + ((size_t)c * PH + ty0 + r) * PW + tx0 + cg * 4);
        *reinterpret_cast<float4*>(sx3 + (c * 14 + r) * 24 + cg * 4) = v;
    }
    __syncthreads();

    int pl = t & 63, sq = t >> 6;
    int pr = pl >> 3, pc = pl & 7;
    const __half2* wp = reinterpret_cast<const __half2*>(swh + pl * KP);
    const float* xb = sx3 + sq * 4 * 336 + pr * 24 + pc;

    float a0 = 0.f, a1 = 0.f, a2 = 0.f, a3 = 0.f;
#pragma unroll
    for (int k2 = 0; k2 < 25; k2++) {
        float2 wf = __half22float2(wp[k2]);
        {
            int k = 2 * k2;
            int xo = (k / 7) * 24 + (k % 7);
            a0 = fmaf(xb[xo],        wf.x, a0);
            a1 = fmaf(xb[336 + xo],  wf.x, a1);
            a2 = fmaf(xb[672 + xo],  wf.x, a2);
            a3 = fmaf(xb[1008 + xo], wf.x, a3);
        }
        if (2 * k2 + 1 < 49) {
            int k = 2 * k2 + 1;
            int xo = (k / 7) * 24 + (k % 7);
            a0 = fmaf(xb[xo],        wf.y, a0);
            a1 = fmaf(xb[336 + xo],  wf.y, a1);
            a2 = fmaf(xb[672 + xo],  wf.y, a2);
            a3 = fmaf(xb[1008 + xo], wf.y, a3);
        }
    }
    int p = (ty0 + pr) * W_ + tx0 + pc;
    float* dst = g_agg + ((size_t)b * OUT_ + g * 8 + sq * 4) * HW + p;
    dst[0] = a0; dst[HW] = a1; dst[2 * HW] = a2; dst[3 * HW] = a3;
}

// ---------------- kernel 4: position2 grouped conv ------------------------
__global__ __launch_bounds__(128) void pos2_kernel(const float* __restrict__ pos2w,
                                                   float* __restrict__ out) {
    __shared__ __align__(16) float sw[64 * KP];
    __shared__ __align__(16) float spw[8 * 60];
    __shared__ float sxv[8 * 64];

    int b = blockIdx.z, g = blockIdx.y, p0 = blockIdx.x * 64;
    int t = threadIdx.x;

    const __half2* gw2 = reinterpret_cast<const __half2*>(g_w);
    size_t base2 = (((size_t)(b * WS_ + g)) * HW + p0) * 26;
    for (int i = t; i < 1664; i += 128) {
        float2 f = __half22float2(gw2[base2 + i]);
        *reinterpret_cast<float2*>(sw + 2 * i) = f;
    }
    for (int i = t; i < 480; i += 128) {
        int o = i / 60, q = i - o * 60;
        spw[i] = (q < 57) ? pos2w[(g * 8 + o) * 57 + q] : 0.0f;
    }
    for (int i = t; i < 512; i += 128) {
        int s = i >> 6, pl = i & 63;
        sxv[i] = g_agg[((size_t)b * OUT_ + s * 32 + g) * HW + p0 + pl];
    }
    __syncthreads();

    int pl = t & 63, oh = t >> 6;
    float acc[4] = {0.f, 0.f, 0.f, 0.f};
#pragma unroll
    for (int s = 0; s < 8; s++) {
        float xv = sxv[s * 64 + pl];
#pragma unroll
        for (int j = 0; j < 4; j++)
            acc[j] = fmaf(xv, spw[(oh * 4 + j) * 60 + s], acc[j]);
    }
    const float4* w4 = reinterpret_cast<const float4*>(sw + pl * KP);
#pragma unroll
    for (int k4 = 0; k4 < 13; k4++) {
        float4 wv = w4[k4];
#pragma unroll
        for (int j = 0; j < 4; j++) {
            float4 pv = *reinterpret_cast<const float4*>(spw + (oh * 4 + j) * 60 + 8 + k4 * 4);
            acc[j] = fmaf(wv.x, pv.x, acc[j]);
            acc[j] = fmaf(wv.y, pv.y, acc[j]);
            acc[j] = fmaf(wv.z, pv.z, acc[j]);
            acc[j] = fmaf(wv.w, pv.w, acc[j]);
        }
    }
#pragma unroll
    for (int j = 0; j < 4; j++)
        out[((size_t)b * OUT_ + g * 8 + oh * 4 + j) * HW + p0 + pl] = acc[j];
}

// ---------------- launch ---------------------------------------------------
extern "C" void kernel_launch(void* const* d_in, const int* in_sizes, int n_in,
                              void* d_out, int out_size) {
    const float* x    = (const float*)d_in[0];
    const float* w1   = (const float*)d_in[1];
    const float* b1   = (const float*)d_in[2];
    const float* w2   = (const float*)d_in[3];
    const float* b2   = (const float*)d_in[4];
    const float* w3   = (const float*)d_in[5];
    const float* b3   = (const float*)d_in[6];
    const float* bn1g = (const float*)d_in[7];
    const float* bn1b = (const float*)d_in[8];
    const float* bn1m = (const float*)d_in[9];
    const float* bn1v = (const float*)d_in[10];
    const float* cw1  = (const float*)d_in[11];
    const float* bn2g = (const float*)d_in[12];
    const float* bn2b = (const float*)d_in[13];
    const float* bn2m = (const float*)d_in[14];
    const float* bn2v = (const float*)d_in[15];
    const float* cw2  = (const float*)d_in[16];
    const float* cb   = (const float*)d_in[17];
    const float* p2w  = (const float*)d_in[18];
    float* out = (float*)d_out;

    pack_kernel<<<(MPROJ * CIN + 255) / 256, 256>>>(w1, b1, w2, b2, w3, b3,
                                                    bn1g, bn1b, bn1m, bn1v, cw1, cw2);

    dim3 gg(HW / BN, MPROJ / BM, B_);
    proj_gemm<<<gg, 256>>>(x);

    const int pad_total = B_ * PC_ * PH * PW;
    pad_kernel<<<(pad_total + 255) / 256, 256>>>();

    attn_kernel<<<dim3(HW / 4, B_), 224>>>(bn2g, bn2b, bn2m, bn2v, cb);

    dim3 ga(49, WS_, B_);
    agg_kernel<<<ga, 128>>>();
    pos2_kernel<<<ga, 128>>>(p2w, out);
}

// round 7
// speedup vs baseline: 1.0294x; 1.0294x over previous
#include <cuda_runtime.h>
#include <cuda_fp16.h>

// ---------------- problem constants ----------------
#define B_    4
#define CIN   256
#define H_    56
#define W_    56
#define HW    3136
#define OUT_  256
#define WS_   32
#define K2    49
#define KP    52
#define MPROJ 288
#define PC_   272
#define PH    62
#define PW    64

// attn dynamic smem layout (bytes)
#define ATT_ACT0   0        // float[392*16]  = 25088
#define ATT_SLOG   25088    // half [256*52]  = 26624
#define ATT_SX2    51712    // float[16*112]  = 7168
#define ATT_CW1    58880    // float[256]     = 1024
#define ATT_CW2    59904    // float[512]     = 2048
#define ATT_SX1    61952    // float[128]     = 512
#define ATT_SCB    62464    // float[32]      = 128
#define ATT_S2S    62592    // float[16]      = 64
#define ATT_T2S    62656    // float[16]      = 64
#define ATT_SINV   62720    // float[256]     = 1024
#define ATT_SMEM   63744

// ---------------- scratch (device globals) --------------------------------
__device__ float  g_wc[MPROJ * CIN];
__device__ float  g_bc[MPROJ];
__device__ float  g_s1[16], g_t1[16];
__device__ float  g_cw1t[256];     // [c][o] transposed
__device__ float  g_cw2t[512];     // [o][g] transposed
__device__ float  g_proj[B_ * MPROJ * HW];
__device__ float  g_pad[(size_t)B_ * PC_ * PH * PW];
__device__ __half g_w[(size_t)B_ * WS_ * HW * KP];
__device__ float  g_agg[B_ * OUT_ * HW];

__device__ __forceinline__ int refl(int i, int n) {
    if (i < 0) i = -i;
    if (i >= n) i = 2 * n - 2 - i;
    return i;
}

// ---------------- kernel 0: pack weights + bn1 fold + transposes ----------
__global__ void pack_kernel(const float* __restrict__ w1, const float* __restrict__ b1,
                            const float* __restrict__ w2, const float* __restrict__ b2,
                            const float* __restrict__ w3, const float* __restrict__ b3,
                            const float* __restrict__ bn1g, const float* __restrict__ bn1b,
                            const float* __restrict__ bn1m, const float* __restrict__ bn1v,
                            const float* __restrict__ cw1, const float* __restrict__ cw2) {
    int i = blockIdx.x * blockDim.x + threadIdx.x;
    if (i < MPROJ * CIN) {
        int r = i / CIN, c = i % CIN;
        float v;
        if (r < 16)      v = w1[r * CIN + c];
        else if (r < 32) v = w2[(r - 16) * CIN + c];
        else             v = w3[(r - 32) * CIN + c];
        g_wc[i] = v;
    }
    if (i < MPROJ) {
        g_bc[i] = (i < 16) ? b1[i] : ((i < 32) ? b2[i - 16] : b3[i - 32]);
    }
    if (i < 16) {
        float s = bn1g[i] * rsqrtf(bn1v[i] + 1e-5f);
        g_s1[i] = s;
        g_t1[i] = bn1b[i] - s * bn1m[i];
    }
    if (i < 256) g_cw1t[i] = cw1[(i & 15) * 16 + (i >> 4)];    // [c][o]
    if (i < 512) g_cw2t[i] = cw2[(i & 31) * 16 + (i >> 5)];    // [o][g]
}

// ---------------- kernel 1: projection GEMM (single-buffered, R5) ---------
#define BM 96
#define BN 64
#define BK 16
__global__ __launch_bounds__(256) void proj_gemm(const float* __restrict__ x) {
    __shared__ float As[BK][BM + 1];
    __shared__ __align__(16) float Bs[BK][BN];

    int b  = blockIdx.z;
    int m0 = blockIdx.y * BM;
    int n0 = blockIdx.x * BN;
    int t  = threadIdx.x;
    int tx = t & 15;
    int ty = t >> 4;

    const float* xb = x + (size_t)b * CIN * HW;

    float acc[6][4];
#pragma unroll
    for (int i = 0; i < 6; i++)
#pragma unroll
        for (int j = 0; j < 4; j++) acc[i][j] = 0.0f;

    for (int k0 = 0; k0 < CIN; k0 += BK) {
#pragma unroll
        for (int q = 0; q < 6; q++) {
            int idx = t + q * 256;
            int col = idx & 15;
            int row = idx >> 4;
            As[col][row] = g_wc[(m0 + row) * CIN + k0 + col];
        }
        {
            int row = t >> 4, cg = t & 15;
            float4 v = *reinterpret_cast<const float4*>(&xb[(size_t)(k0 + row) * HW + n0 + cg * 4]);
            *reinterpret_cast<float4*>(&Bs[row][cg * 4]) = v;
        }
        __syncthreads();
#pragma unroll
        for (int k = 0; k < BK; k++) {
            float a[6];
#pragma unroll
            for (int i = 0; i < 6; i++) a[i] = As[k][ty * 6 + i];
            float4 bv = *reinterpret_cast<float4*>(&Bs[k][tx * 4]);
            float bb[4] = {bv.x, bv.y, bv.z, bv.w};
#pragma unroll
            for (int i = 0; i < 6; i++)
#pragma unroll
                for (int j = 0; j < 4; j++) acc[i][j] = fmaf(a[i], bb[j], acc[i][j]);
        }
        __syncthreads();
    }
#pragma unroll
    for (int i = 0; i < 6; i++) {
        int m = m0 + ty * 6 + i;
        float bias = g_bc[m];
        float vv[4];
#pragma unroll
        for (int j = 0; j < 4; j++) vv[j] = acc[i][j] + bias;
        if (m < 16) {
            float s = g_s1[m], tt = g_t1[m];
#pragma unroll
            for (int j = 0; j < 4; j++) vv[j] = fmaf(s, vv[j], tt);
        } else if (m < 32) {
            float s = g_s1[m - 16];
#pragma unroll
            for (int j = 0; j < 4; j++) vv[j] *= s;
        }
        float4 v = make_float4(vv[0], vv[1], vv[2], vv[3]);
        *reinterpret_cast<float4*>(&g_proj[((size_t)b * MPROJ + m) * HW + n0 + tx * 4]) = v;
    }
}

// ---------------- kernel 1b: reflect-pad channels 16..287 -----------------
__global__ void pad_kernel() {
    int idx = blockIdx.x * 256 + threadIdx.x;
    const int total = B_ * PC_ * PH * PW;
    if (idx >= total) return;
    int col = idx & 63;
    int rest = idx >> 6;
    int r = rest % PH;
    int cb = rest / PH;
    int c = cb % PC_;
    int b = cb / PC_;
    int oy = refl(r - 3, H_), ox = refl(col - 3, W_);
    g_pad[idx] = g_proj[((size_t)(b * MPROJ + 16 + c)) * HW + oy * W_ + ox];
}

// ---------------- kernel 2: attention weights + softmax (8 px / block) ----
__global__ __launch_bounds__(384, 3) void attn_kernel(
    const float* __restrict__ bn2g, const float* __restrict__ bn2b,
    const float* __restrict__ bn2m, const float* __restrict__ bn2v,
    const float* __restrict__ cb) {

    extern __shared__ __align__(16) char smem_raw[];
    float*  act0  = (float*)(smem_raw + ATT_ACT0);    // [392][16]
    __half* slog  = (__half*)(smem_raw + ATT_SLOG);   // [256][52]
    float*  sx2   = (float*)(smem_raw + ATT_SX2);     // [16][112] (dy*16+col)
    float*  scw1t = (float*)(smem_raw + ATT_CW1);     // [c][o]
    float*  scw2t = (float*)(smem_raw + ATT_CW2);     // [o][g]
    float*  sx1   = (float*)(smem_raw + ATT_SX1);     // [pix*16+c]
    float*  scb   = (float*)(smem_raw + ATT_SCB);
    float*  s2s   = (float*)(smem_raw + ATT_S2S);
    float*  t2s   = (float*)(smem_raw + ATT_T2S);
    float*  sinv  = (float*)(smem_raw + ATT_SINV);    // [256]

    int t = threadIdx.x;
    int b = blockIdx.y;
    int p0 = blockIdx.x * 8;          // 8 consecutive pixels, same row
    int h = p0 / W_, w0 = p0 % W_;    // w0 in {0,8,...,48}

    // -------- staging --------
    if (t < 64)
        reinterpret_cast<float4*>(scw1t)[t] = reinterpret_cast<const float4*>(g_cw1t)[t];
    else if (t < 192)
        reinterpret_cast<float4*>(scw2t)[t - 64] = reinterpret_cast<const float4*>(g_cw2t)[t - 64];
    else if (t < 224) {
        scb[t - 192] = cb[t - 192];
    } else if (t < 240) {
        int c = t - 224;
        float ss = bn2g[c] * rsqrtf(bn2v[c] + 1e-5f);
        s2s[c] = ss; t2s[c] = bn2b[c] - ss * bn2m[c];
    } else if (t < 368) {
        int idx = t - 240;             // 0..127
        int c = idx >> 3, pix = idx & 7;
        sx1[pix * 16 + c] = g_proj[((size_t)b * MPROJ + c) * HW + p0 + pix];
    }
    // x2' window: 16 ch x 7 rows x 16 cols (cols w0..w0+15, rows h..h+6)
    const float* padb = g_pad + (size_t)b * PC_ * PH * PW;
    for (int i = t; i < 448; i += 384) {
        int c = i / 28, rem = i - c * 28, dy = rem >> 2, cg = rem & 3;
        float4 v = *reinterpret_cast<const float4*>(
            padb + ((size_t)c * PH + h + dy) * PW + w0 + cg * 4);
        *reinterpret_cast<float4*>(sx2 + c * 112 + dy * 16 + cg * 4) = v;
    }
    __syncthreads();

    // -------- phase1: relu(x1' - x2') --------
    for (int pt = t; pt < 392; pt += 384) {
        int pix = pt / 49, k = pt - pix * 49;
        int dy = k / 7, dx = k - dy * 7;
        const float* x2p = sx2 + dy * 16 + dx + pix;
        const float* x1p = sx1 + pix * 16;
        float av[16];
#pragma unroll
        for (int c = 0; c < 16; c++) av[c] = fmaxf(x1p[c] - x2p[c * 112], 0.0f);
        float4* dst = reinterpret_cast<float4*>(act0 + pt * 16);
#pragma unroll
        for (int q = 0; q < 4; q++)
            dst[q] = make_float4(av[q * 4], av[q * 4 + 1], av[q * 4 + 2], av[q * 4 + 3]);
    }
    __syncthreads();

    // -------- phase2: GEMM1 (16->16) + BN2 + ReLU, in place --------
    // thread = (o-pair 0..7, pb 0..47); rows pt = pb + 48n
    {
        int op = t & 7, pb = t >> 3;
        int o0 = op * 2;
        float2 w1r[16];
#pragma unroll
        for (int c = 0; c < 16; c++)
            w1r[c] = *reinterpret_cast<const float2*>(scw1t + c * 16 + o0);
        float s2a = s2s[o0], s2b = s2s[o0 + 1];
        float t2a = t2s[o0], t2b = t2s[o0 + 1];
        for (int pt = pb; pt < 392; pt += 48) {
            const float4* ap = reinterpret_cast<const float4*>(act0 + pt * 16);
            float a[16];
            *reinterpret_cast<float4*>(a + 0)  = ap[0];
            *reinterpret_cast<float4*>(a + 4)  = ap[1];
            *reinterpret_cast<float4*>(a + 8)  = ap[2];
            *reinterpret_cast<float4*>(a + 12) = ap[3];
            float h0 = 0.0f, h1 = 0.0f;
#pragma unroll
            for (int c = 0; c < 16; c++) {
                h0 = fmaf(a[c], w1r[c].x, h0);
                h1 = fmaf(a[c], w1r[c].y, h1);
            }
            __syncwarp();
            float r0 = fmaxf(fmaf(s2a, h0, t2a), 0.0f);
            float r1 = fmaxf(fmaf(s2b, h1, t2b), 0.0f);
            *reinterpret_cast<float2*>(act0 + pt * 16 + o0) = make_float2(r0, r1);
            __syncwarp();
        }
    }
    __syncthreads();

    // -------- phase3: GEMM2 (16->32) + bias -> fp16 logits --------
    // thread = (g-pair 0..15, pb 0..23); rows pt = pb + 24n
    {
        int gp = t & 15, pb = t >> 4;
        int g0 = gp * 2;
        float2 w2r[16];
#pragma unroll
        for (int o = 0; o < 16; o++)
            w2r[o] = *reinterpret_cast<const float2*>(scw2t + o * 32 + g0);
        float bias0 = scb[g0], bias1 = scb[g0 + 1];
        int pix = 0, k = pb;
        for (int pt = pb; pt < 392; pt += 24) {
            const float4* ap = reinterpret_cast<const float4*>(act0 + pt * 16);
            float a[16];
            *reinterpret_cast<float4*>(a + 0)  = ap[0];
            *reinterpret_cast<float4*>(a + 4)  = ap[1];
            *reinterpret_cast<float4*>(a + 8)  = ap[2];
            *reinterpret_cast<float4*>(a + 12) = ap[3];
            float h0 = bias0, h1 = bias1;
#pragma unroll
            for (int o = 0; o < 16; o++) {
                h0 = fmaf(a[o], w2r[o].x, h0);
                h1 = fmaf(a[o], w2r[o].y, h1);
            }
            int rowb = (pix * 32 + g0) * 52 + k;
            slog[rowb]      = __float2half(h0);
            slog[rowb + 52] = __float2half(h1);
            k += 24;
            if (k >= 49) { k -= 49; pix++; }
        }
    }
    __syncthreads();

    // -------- phase4: softmax (exp in place, keep 1/sum) --------
    if (t < 256) {
        __half2* row = reinterpret_cast<__half2*>(slog) + t * 26;
        float m = -1e30f;
#pragma unroll
        for (int k2 = 0; k2 < 24; k2++) {
            float2 f = __half22float2(row[k2]);
            m = fmaxf(m, fmaxf(f.x, f.y));
        }
        m = fmaxf(m, __half22float2(row[24]).x);
        float s = 0.0f;
#pragma unroll
        for (int k2 = 0; k2 < 24; k2++) {
            float2 f = __half22float2(row[k2]);
            float ex = __expf(f.x - m), ey = __expf(f.y - m);
            s += ex + ey;
            row[k2] = __floats2half2_rn(ex, ey);
        }
        {
            float ex = __expf(__half22float2(row[24]).x - m);
            s += ex;
            row[24] = __floats2half2_rn(ex, 0.0f);
            row[25] = __floats2half2_rn(0.0f, 0.0f);
        }
        sinv[t] = 1.0f / s;
    }
    __syncthreads();

    // -------- phase5: scale + write fp16 g_w --------
    // 6656 half2 total; stride 384 = 14*26 + 20
    {
        __half2* gw2 = reinterpret_cast<__half2*>(g_w);
        const __half2* sl2 = reinterpret_cast<const __half2*>(slog);
        int r = t / 26, k2 = t - r * 26;
        for (int i = t; i < 6656; i += 384) {
            int pix = r >> 5, g = r & 31;
            float2 f = __half22float2(sl2[r * 26 + k2]);
            float inv = sinv[r];
            gw2[(((size_t)(b * WS_ + g)) * HW + p0 + pix) * 26 + k2] =
                __floats2half2_rn(f.x * inv, f.y * inv);
            r += 14; k2 += 20;
            if (k2 >= 26) { k2 -= 26; r++; }
        }
    }
}

// ---------------- kernel 3: aggregation -----------------------------------
__global__ __launch_bounds__(128) void agg_kernel() {
    __shared__ __align__(4) __half swh[64 * KP];
    __shared__ __align__(16) float sx3[8 * 14 * 24];

    int b = blockIdx.z, g = blockIdx.y, tile = blockIdx.x;
    int ty0 = (tile / 7) * 8, tx0 = (tile % 7) * 8;
    int t = threadIdx.x;

    const __half2* gw2 = reinterpret_cast<const __half2*>(g_w);
    size_t wbase = ((size_t)(b * WS_ + g)) * HW;
    for (int i = t; i < 1664; i += 128) {
        int run = i / 208, off = i - run * 208;
        reinterpret_cast<__half2*>(swh)[run * 208 + off] =
            gw2[(wbase + (ty0 + run) * W_ + tx0) * 26 + off];
    }
    const float* padb = g_pad + ((size_t)(b * PC_) + 16 + g * 8) * PH * PW;
    for (int i = t; i < 448; i += 128) {
        int c = i / 56, rem = i - c * 56, r = rem >> 2, cg = rem & 3;
        float4 v = *reinterpret_cast<const float4*>(
            padb + ((size_t)c * PH + ty0 + r) * PW + tx0 + cg * 4);
        *reinterpret_cast<float4*>(sx3 + (c * 14 + r) * 24 + cg * 4) = v;
    }
    __syncthreads();

    int pl = t & 63, sq = t >> 6;
    int pr = pl >> 3, pc = pl & 7;
    const __half2* wp = reinterpret_cast<const __half2*>(swh + pl * KP);
    const float* xb = sx3 + sq * 4 * 336 + pr * 24 + pc;

    float a0 = 0.f, a1 = 0.f, a2 = 0.f, a3 = 0.f;
#pragma unroll
    for (int k2 = 0; k2 < 25; k2++) {
        float2 wf = __half22float2(wp[k2]);
        {
            int k = 2 * k2;
            int xo = (k / 7) * 24 + (k % 7);
            a0 = fmaf(xb[xo],        wf.x, a0);
            a1 = fmaf(xb[336 + xo],  wf.x, a1);
            a2 = fmaf(xb[672 + xo],  wf.x, a2);
            a3 = fmaf(xb[1008 + xo], wf.x, a3);
        }
        if (2 * k2 + 1 < 49) {
            int k = 2 * k2 + 1;
            int xo = (k / 7) * 24 + (k % 7);
            a0 = fmaf(xb[xo],        wf.y, a0);
            a1 = fmaf(xb[336 + xo],  wf.y, a1);
            a2 = fmaf(xb[672 + xo],  wf.y, a2);
            a3 = fmaf(xb[1008 + xo], wf.y, a3);
        }
    }
    int p = (ty0 + pr) * W_ + tx0 + pc;
    float* dst = g_agg + ((size_t)b * OUT_ + g * 8 + sq * 4) * HW + p;
    dst[0] = a0; dst[HW] = a1; dst[2 * HW] = a2; dst[3 * HW] = a3;
}

// ---------------- kernel 4: position2 grouped conv ------------------------
__global__ __launch_bounds__(128) void pos2_kernel(const float* __restrict__ pos2w,
                                                   float* __restrict__ out) {
    __shared__ __align__(16) float sw[64 * KP];
    __shared__ __align__(16) float spw[8 * 60];
    __shared__ float sxv[8 * 64];

    int b = blockIdx.z, g = blockIdx.y, p0 = blockIdx.x * 64;
    int t = threadIdx.x;

    const __half2* gw2 = reinterpret_cast<const __half2*>(g_w);
    size_t base2 = (((size_t)(b * WS_ + g)) * HW + p0) * 26;
    for (int i = t; i < 1664; i += 128) {
        float2 f = __half22float2(gw2[base2 + i]);
        *reinterpret_cast<float2*>(sw + 2 * i) = f;
    }
    for (int i = t; i < 480; i += 128) {
        int o = i / 60, q = i - o * 60;
        spw[i] = (q < 57) ? pos2w[(g * 8 + o) * 57 + q] : 0.0f;
    }
    for (int i = t; i < 512; i += 128) {
        int s = i >> 6, pl = i & 63;
        sxv[i] = g_agg[((size_t)b * OUT_ + s * 32 + g) * HW + p0 + pl];
    }
    __syncthreads();

    int pl = t & 63, oh = t >> 6;
    float acc[4] = {0.f, 0.f, 0.f, 0.f};
#pragma unroll
    for (int s = 0; s < 8; s++) {
        float xv = sxv[s * 64 + pl];
#pragma unroll
        for (int j = 0; j < 4; j++)
            acc[j] = fmaf(xv, spw[(oh * 4 + j) * 60 + s], acc[j]);
    }
    const float4* w4 = reinterpret_cast<const float4*>(sw + pl * KP);
#pragma unroll
    for (int k4 = 0; k4 < 13; k4++) {
        float4 wv = w4[k4];
#pragma unroll
        for (int j = 0; j < 4; j++) {
            float4 pv = *reinterpret_cast<const float4*>(spw + (oh * 4 + j) * 60 + 8 + k4 * 4);
            acc[j] = fmaf(wv.x, pv.x, acc[j]);
            acc[j] = fmaf(wv.y, pv.y, acc[j]);
            acc[j] = fmaf(wv.z, pv.z, acc[j]);
            acc[j] = fmaf(wv.w, pv.w, acc[j]);
        }
    }
#pragma unroll
    for (int j = 0; j < 4; j++)
        out[((size_t)b * OUT_ + g * 8 + oh * 4 + j) * HW + p0 + pl] = acc[j];
}

// ---------------- launch ---------------------------------------------------
extern "C" void kernel_launch(void* const* d_in, const int* in_sizes, int n_in,
                              void* d_out, int out_size) {
    const float* x    = (const float*)d_in[0];
    const float* w1   = (const float*)d_in[1];
    const float* b1   = (const float*)d_in[2];
    const float* w2   = (const float*)d_in[3];
    const float* b2   = (const float*)d_in[4];
    const float* w3   = (const float*)d_in[5];
    const float* b3   = (const float*)d_in[6];
    const float* bn1g = (const float*)d_in[7];
    const float* bn1b = (const float*)d_in[8];
    const float* bn1m = (const float*)d_in[9];
    const float* bn1v = (const float*)d_in[10];
    const float* cw1  = (const float*)d_in[11];
    const float* bn2g = (const float*)d_in[12];
    const float* bn2b = (const float*)d_in[13];
    const float* bn2m = (const float*)d_in[14];
    const float* bn2v = (const float*)d_in[15];
    const float* cw2  = (const float*)d_in[16];
    const float* cb   = (const float*)d_in[17];
    const float* p2w  = (const float*)d_in[18];
    float* out = (float*)d_out;

    cudaFuncSetAttribute(attn_kernel, cudaFuncAttributeMaxDynamicSharedMemorySize, ATT_SMEM);

    pack_kernel<<<(MPROJ * CIN + 255) / 256, 256>>>(w1, b1, w2, b2, w3, b3,
                                                    bn1g, bn1b, bn1m, bn1v, cw1, cw2);

    dim3 gg(HW / BN, MPROJ / BM, B_);
    proj_gemm<<<gg, 256>>>(x);

    const int pad_total = B_ * PC_ * PH * PW;
    pad_kernel<<<(pad_total + 255) / 256, 256>>>();

    attn_kernel<<<dim3(HW / 8, B_), 384, ATT_SMEM>>>(bn2g, bn2b, bn2m, bn2v, cb);

    dim3 ga(49, WS_, B_);
    agg_kernel<<<ga, 128>>>();
    pos2_kernel<<<ga, 128>>>(p2w, out);
}